// round 12
// baseline (speedup 1.0000x reference)
#include <cuda_runtime.h>
#include <cstdint>

#define N_NODES 50000
#define M_PAD   50048          // 391 * 128
#define GRID_M  391
#define N_EDGES 600000
#define F_IN 128
#define DIM_H 256
#define N_CLASSES 40
#define BN_EPS 1e-5f

// ---------------- scratch (static __device__, no allocation) ----------------
__device__ float  g_h0[(size_t)M_PAD * F_IN];     // x + agg   (padding rows stay 0)
__device__ float  g_h1[(size_t)M_PAD * DIM_H];    // GEMM1 out, then BN+ReLU in place
__device__ float  g_h2[(size_t)M_PAD * DIM_H];    // GEMM2 out
__device__ float  g_Bt1[DIM_H * F_IN];            // W1^T  [256][128]  (tf32-rounded)
__device__ float  g_Bt2[DIM_H * DIM_H];           // W2^T  [256][256]
__device__ float  g_Bt3[N_CLASSES * DIM_H];       // Wlin^T [40][256]
__device__ float  g_psum[GRID_M * DIM_H];         // per-CTA column sums of h1
__device__ float  g_psq [GRID_M * DIM_H];         // per-CTA column sumsq
__device__ float  g_scale[DIM_H];
__device__ float  g_shift[DIM_H];
__device__ int    g_is64;

// ---------------- PTX helpers (all sm_80-compatible, no arch-'a' features) ----
__device__ __forceinline__ uint32_t smem_u32(const void* p) {
    uint32_t a;
    asm("{ .reg .u64 t; cvta.to.shared.u64 t, %1; cvt.u32.u64 %0, t; }" : "=r"(a) : "l"(p));
    return a;
}
__device__ __forceinline__ void cp_async16(uint32_t dst, const void* src) {
    asm volatile("cp.async.cg.shared.global [%0], [%1], 16;" :: "r"(dst), "l"(src));
}
__device__ __forceinline__ void cp_commit() {
    asm volatile("cp.async.commit_group;" ::: "memory");
}
template<int N>
__device__ __forceinline__ void cp_wait() {
    asm volatile("cp.async.wait_group %0;" :: "n"(N) : "memory");
}
__device__ __forceinline__ void ldsm_x4(uint32_t& r0, uint32_t& r1, uint32_t& r2, uint32_t& r3,
                                        uint32_t addr) {
    asm volatile("ldmatrix.sync.aligned.m8n8.x4.shared.b16 {%0,%1,%2,%3}, [%4];"
                 : "=r"(r0), "=r"(r1), "=r"(r2), "=r"(r3) : "r"(addr));
}
__device__ __forceinline__ void mma_tf32(float* c, const uint32_t* a, const uint32_t* b) {
    asm volatile("mma.sync.aligned.m16n8k8.row.col.f32.tf32.tf32.f32 "
                 "{%0,%1,%2,%3}, {%4,%5,%6,%7}, {%8,%9}, {%0,%1,%2,%3};"
                 : "+f"(c[0]), "+f"(c[1]), "+f"(c[2]), "+f"(c[3])
                 : "r"(a[0]), "r"(a[1]), "r"(a[2]), "r"(a[3]), "r"(b[0]), "r"(b[1]));
}
__device__ __forceinline__ uint32_t rna_tf32(float f) {
    uint32_t r;
    asm("cvt.rna.tf32.f32 %0, %1;" : "=r"(r) : "f"(f));
    return r;
}

// ---------------- prep: dtype detect + weight transposes ----------------
__global__ void prep_kernel(const int* __restrict__ ei,
                            const float* __restrict__ W1,
                            const float* __restrict__ W2,
                            const float* __restrict__ Wlin) {
    int tid = threadIdx.x;
    if (blockIdx.x == 0) {
        __shared__ int nz;
        if (tid == 0) nz = 0;
        __syncthreads();
        if (ei[2 * tid + 1] != 0) atomicOr(&nz, 1);
        __syncthreads();
        if (tid == 0) g_is64 = (nz == 0) ? 1 : 0;
    }
    int g = blockIdx.x * blockDim.x + tid;
    int stride = gridDim.x * blockDim.x;
    uint32_t* B1 = reinterpret_cast<uint32_t*>(g_Bt1);
    uint32_t* B2 = reinterpret_cast<uint32_t*>(g_Bt2);
    uint32_t* B3 = reinterpret_cast<uint32_t*>(g_Bt3);
    for (int i = g; i < F_IN * DIM_H; i += stride) {
        int k = i / DIM_H, n = i - k * DIM_H;
        B1[n * F_IN + k] = rna_tf32(W1[i]);
    }
    for (int i = g; i < DIM_H * DIM_H; i += stride) {
        int k = i / DIM_H, n = i - k * DIM_H;
        B2[n * DIM_H + k] = rna_tf32(W2[i]);
    }
    for (int i = g; i < DIM_H * N_CLASSES; i += stride) {
        int k = i / N_CLASSES, n = i - k * N_CLASSES;
        B3[n * DIM_H + k] = rna_tf32(Wlin[i]);
    }
}

// ---------------- h0 = x ----------------
__global__ void copy_x_kernel(const float4* __restrict__ x4) {
    int i = blockIdx.x * blockDim.x + threadIdx.x;
    const int n = N_NODES * F_IN / 4;
    if (i < n) reinterpret_cast<float4*>(g_h0)[i] = x4[i];
}

// ---------------- scatter: h0[dst] += x[src], warp per edge ----------------
__global__ void scatter_kernel(const float* __restrict__ x, const void* __restrict__ eiv) {
    int gid = blockIdx.x * blockDim.x + threadIdx.x;
    int e = gid >> 5;
    if (e >= N_EDGES) return;
    int lane = gid & 31;
    long long s, d;
    if (g_is64) {
        const long long* ei = (const long long*)eiv;
        s = ei[e]; d = ei[N_EDGES + e];
    } else {
        const int* ei = (const int*)eiv;
        s = ei[e]; d = ei[N_EDGES + e];
    }
    float4 v = reinterpret_cast<const float4*>(x + s * F_IN)[lane];
    float* p = g_h0 + d * F_IN + lane * 4;
    asm volatile("red.global.add.v4.f32 [%0], {%1, %2, %3, %4};"
                 :: "l"(p), "f"(v.x), "f"(v.y), "f"(v.z), "f"(v.w) : "memory");
}

// ---------------- tf32 mma.sync GEMM (R8 proven): 256 thr, warp tile 64x32 ---
// Used for the ragged-N GEMM3 only.
template<int BN, int WARPS_M, int WARPS_N, bool HAS_BIAS, bool RELU>
__global__ void __launch_bounds__(256, 2) mma_gemm_kernel(
    const float* __restrict__ A, const float* __restrict__ Bt,
    const float* __restrict__ bias, float* __restrict__ C,
    int M, int K, int Nreal)
{
    constexpr int KC = 32;                 // floats per K chunk (= 128B row)
    constexpr int WTM = 128 / WARPS_M;
    constexpr int WTN = BN / WARPS_N;
    constexpr int RM = WTM / 16;
    constexpr int RN = WTN / 8;
    constexpr int A_BYTES = 128 * 128;
    constexpr int B_BYTES = BN * 128;
    constexpr int BUF = A_BYTES + B_BYTES;
    extern __shared__ __align__(128) char smem[];
    const uint32_t sbase = smem_u32(smem);

    const int tid = threadIdx.x, wid = tid >> 5, lane = tid & 31;
    const int wm = wid % WARPS_M, wn = wid / WARPS_M;
    const int m0 = blockIdx.x * 128;
    const int n0cta = blockIdx.y * BN;
    const int nb_valid = Nreal - n0cta;    // B rows present in this CTA's n-slice
    const int nchunks = K / KC;

    // zero B buffers only when the n-slice is ragged (GEMM3)
    if (nb_valid < BN) {
        for (int i = tid; i < 2 * B_BYTES / 16; i += 256) {
            int b = i / (B_BYTES / 16), j = i % (B_BYTES / 16);
            *reinterpret_cast<float4*>(smem + b * BUF + A_BYTES + j * 16) =
                make_float4(0.f, 0.f, 0.f, 0.f);
        }
    }
    __syncthreads();

    auto load_chunk = [&](int c) {
        const uint32_t abuf = sbase + (c & 1) * BUF;
        const uint32_t bbuf = abuf + A_BYTES;
        const float* Ab = A + (size_t)m0 * K + c * KC;
        #pragma unroll
        for (int i = 0; i < 4; i++) {
            int f = tid + i * 256;         // 0..1023
            int row = f >> 3, kc = f & 7;
            cp_async16(abuf + row * 128 + ((kc ^ (row & 7)) << 4),
                       Ab + (size_t)row * K + kc * 4);
        }
        const float* Bb = Bt + (size_t)n0cta * K + c * KC;
        #pragma unroll
        for (int i = 0; i < BN * 8 / 256; i++) {
            int f = tid + i * 256;
            int row = f >> 3, kc = f & 7;
            if (row < nb_valid)
                cp_async16(bbuf + row * 128 + ((kc ^ (row & 7)) << 4),
                           Bb + (size_t)row * K + kc * 4);
        }
        cp_commit();
    };

    load_chunk(0);
    load_chunk(1);

    float acc[RM][RN][4] = {};

    for (int c = 0; c < nchunks; c++) {
        if (c + 1 < nchunks) cp_wait<1>(); else cp_wait<0>();
        __syncthreads();

        const uint32_t abuf = sbase + (c & 1) * BUF;
        const uint32_t bbuf = abuf + A_BYTES;
        #pragma unroll
        for (int ks = 0; ks < 4; ks++) {
            uint32_t af[RM][4], bf[RN][2];
            #pragma unroll
            for (int mt = 0; mt < RM; mt++) {
                int row = wm * WTM + mt * 16 + (lane & 15);
                int kc = ks * 2 + (lane >> 4);
                ldsm_x4(af[mt][0], af[mt][1], af[mt][2], af[mt][3],
                        abuf + row * 128 + ((kc ^ (row & 7)) << 4));
            }
            #pragma unroll
            for (int nt = 0; nt < RN; nt += 2) {
                int row = wn * WTN + nt * 8 + ((lane >> 4) & 1) * 8 + (lane & 7);
                int kc = ks * 2 + ((lane >> 3) & 1);
                ldsm_x4(bf[nt][0], bf[nt][1], bf[nt + 1][0], bf[nt + 1][1],
                        bbuf + row * 128 + ((kc ^ (row & 7)) << 4));
            }
            #pragma unroll
            for (int mt = 0; mt < RM; mt++)
                #pragma unroll
                for (int nt = 0; nt < RN; nt++)
                    mma_tf32(acc[mt][nt], af[mt], bf[nt]);
        }
        __syncthreads();
        if (c + 2 < nchunks) load_chunk(c + 2);
    }

    // epilogue
    #pragma unroll
    for (int mt = 0; mt < RM; mt++) {
        int r0 = m0 + wm * WTM + mt * 16 + (lane >> 2);
        #pragma unroll
        for (int nt = 0; nt < RN; nt++) {
            int n = n0cta + wn * WTN + nt * 8 + (lane & 3) * 2;
            if (n >= Nreal) continue;      // Nreal even -> pair fully valid
            float2 v0 = make_float2(acc[mt][nt][0], acc[mt][nt][1]);
            float2 v1 = make_float2(acc[mt][nt][2], acc[mt][nt][3]);
            if (HAS_BIAS) {
                float2 bb = *reinterpret_cast<const float2*>(bias + n);
                v0.x += bb.x; v0.y += bb.y; v1.x += bb.x; v1.y += bb.y;
            }
            if (RELU) {
                v0.x = fmaxf(v0.x, 0.f); v0.y = fmaxf(v0.y, 0.f);
                v1.x = fmaxf(v1.x, 0.f); v1.y = fmaxf(v1.y, 0.f);
            }
            if (r0 < M)
                *reinterpret_cast<float2*>(C + (size_t)r0 * Nreal + n) = v0;
            if (r0 + 8 < M)
                *reinterpret_cast<float2*>(C + (size_t)(r0 + 8) * Nreal + n) = v1;
        }
    }
}

// ---------------- big-tile tf32 GEMM: 128 thr, 64x64/warp, optional STATS ----
// CTA 128x128, 2x2 warps, RM=4, RN=8. Requires Nreal % 128 == 0.
// STATS (GEMM1 only): per-CTA column sum/sumsq of C written to g_psum/g_psq.
// No bounds checks needed: h0 padding rows are zero and GEMM1 has no bias, so
// padding rows of C are exactly zero and contribute nothing.
template<bool HAS_BIAS, bool RELU, bool STATS>
__global__ void __launch_bounds__(128, 2) mma_gemm_big(
    const float* __restrict__ A, const float* __restrict__ Bt,
    const float* __restrict__ bias, float* __restrict__ C,
    int M, int K, int Nreal)
{
    constexpr int KC = 32;
    constexpr int BN = 128;
    constexpr int RM = 4, RN = 8;          // 64x64 per warp
    constexpr int A_BYTES = 128 * 128;
    constexpr int B_BYTES = BN * 128;
    constexpr int BUF = A_BYTES + B_BYTES;
    extern __shared__ __align__(128) char smem[];
    const uint32_t sbase = smem_u32(smem);

    const int tid = threadIdx.x, wid = tid >> 5, lane = tid & 31;
    const int wm = wid & 1, wn = wid >> 1; // 2x2 warp grid
    const int m0 = blockIdx.x * 128;
    const int n0cta = blockIdx.y * BN;
    const int nchunks = K / KC;

    auto load_chunk = [&](int c) {
        const uint32_t abuf = sbase + (c & 1) * BUF;
        const uint32_t bbuf = abuf + A_BYTES;
        const float* Ab = A + (size_t)m0 * K + c * KC;
        #pragma unroll
        for (int i = 0; i < 8; i++) {
            int f = tid + i * 128;         // 0..1023
            int row = f >> 3, kc = f & 7;
            cp_async16(abuf + row * 128 + ((kc ^ (row & 7)) << 4),
                       Ab + (size_t)row * K + kc * 4);
        }
        const float* Bb = Bt + (size_t)n0cta * K + c * KC;
        #pragma unroll
        for (int i = 0; i < 8; i++) {
            int f = tid + i * 128;
            int row = f >> 3, kc = f & 7;
            cp_async16(bbuf + row * 128 + ((kc ^ (row & 7)) << 4),
                       Bb + (size_t)row * K + kc * 4);
        }
        cp_commit();
    };

    load_chunk(0);
    load_chunk(1);

    float acc[RM][RN][4] = {};

    for (int c = 0; c < nchunks; c++) {
        if (c + 1 < nchunks) cp_wait<1>(); else cp_wait<0>();
        __syncthreads();

        const uint32_t abuf = sbase + (c & 1) * BUF;
        const uint32_t bbuf = abuf + A_BYTES;
        #pragma unroll
        for (int ks = 0; ks < 4; ks++) {
            uint32_t af[RM][4], bf[RN][2];
            #pragma unroll
            for (int mt = 0; mt < RM; mt++) {
                int row = wm * 64 + mt * 16 + (lane & 15);
                int kc = ks * 2 + (lane >> 4);
                ldsm_x4(af[mt][0], af[mt][1], af[mt][2], af[mt][3],
                        abuf + row * 128 + ((kc ^ (row & 7)) << 4));
            }
            #pragma unroll
            for (int nt = 0; nt < RN; nt += 2) {
                int row = wn * 64 + nt * 8 + ((lane >> 4) & 1) * 8 + (lane & 7);
                int kc = ks * 2 + ((lane >> 3) & 1);
                ldsm_x4(bf[nt][0], bf[nt][1], bf[nt + 1][0], bf[nt + 1][1],
                        bbuf + row * 128 + ((kc ^ (row & 7)) << 4));
            }
            #pragma unroll
            for (int mt = 0; mt < RM; mt++)
                #pragma unroll
                for (int nt = 0; nt < RN; nt++)
                    mma_tf32(acc[mt][nt], af[mt], bf[nt]);
        }
        __syncthreads();
        if (c + 2 < nchunks) load_chunk(c + 2);
    }

    // store epilogue
    #pragma unroll
    for (int mt = 0; mt < RM; mt++) {
        int r0 = m0 + wm * 64 + mt * 16 + (lane >> 2);
        #pragma unroll
        for (int nt = 0; nt < RN; nt++) {
            int n = n0cta + wn * 64 + nt * 8 + (lane & 3) * 2;
            float2 v0 = make_float2(acc[mt][nt][0], acc[mt][nt][1]);
            float2 v1 = make_float2(acc[mt][nt][2], acc[mt][nt][3]);
            if (HAS_BIAS) {
                float2 bb = *reinterpret_cast<const float2*>(bias + n);
                v0.x += bb.x; v0.y += bb.y; v1.x += bb.x; v1.y += bb.y;
            }
            if (RELU) {
                v0.x = fmaxf(v0.x, 0.f); v0.y = fmaxf(v0.y, 0.f);
                v1.x = fmaxf(v1.x, 0.f); v1.y = fmaxf(v1.y, 0.f);
            }
            if (r0 < M)
                *reinterpret_cast<float2*>(C + (size_t)r0 * Nreal + n) = v0;
            if (r0 + 8 < M)
                *reinterpret_cast<float2*>(C + (size_t)(r0 + 8) * Nreal + n) = v1;
        }
    }

    // fused BN-stats epilogue (GEMM1 only)
    if constexpr (STATS) {
        __shared__ float ssum[2][128], ssq[2][128];
        #pragma unroll
        for (int nt = 0; nt < RN; nt++) {
            float s0 = 0.f, s1 = 0.f, q0 = 0.f, q1 = 0.f;
            #pragma unroll
            for (int mt = 0; mt < RM; mt++) {
                float v = acc[mt][nt][0]; s0 += v; q0 += v * v;
                v = acc[mt][nt][1];       s1 += v; q1 += v * v;
                v = acc[mt][nt][2];       s0 += v; q0 += v * v;
                v = acc[mt][nt][3];       s1 += v; q1 += v * v;
            }
            // reduce over the 8 lanes sharing (lane & 3)
            #pragma unroll
            for (int mk = 4; mk < 32; mk <<= 1) {
                s0 += __shfl_xor_sync(0xFFFFFFFFu, s0, mk);
                s1 += __shfl_xor_sync(0xFFFFFFFFu, s1, mk);
                q0 += __shfl_xor_sync(0xFFFFFFFFu, q0, mk);
                q1 += __shfl_xor_sync(0xFFFFFFFFu, q1, mk);
            }
            if (lane < 4) {
                int cl = wn * 64 + nt * 8 + lane * 2;
                ssum[wm][cl] = s0; ssum[wm][cl + 1] = s1;
                ssq [wm][cl] = q0; ssq [wm][cl + 1] = q1;
            }
        }
        __syncthreads();
        if (tid < 128) {
            int idx = (blockIdx.x * 2 + blockIdx.y) * 128 + tid;
            g_psum[idx] = ssum[0][tid] + ssum[1][tid];
            g_psq [idx] = ssq [0][tid] + ssq [1][tid];
        }
    }
}

// ---------------- finalize: reduce per-CTA partials -> scale/shift ----------
__global__ void finalize_psum_kernel(const float* __restrict__ gamma,
                                     const float* __restrict__ beta) {
    __shared__ double sh_s[4][DIM_H], sh_q[4][DIM_H];
    int t = threadIdx.x;              // 1024
    int c = t & 255, part = t >> 8;
    int b0 = part * 98, b1 = min(b0 + 98, GRID_M);
    double s = 0.0, q = 0.0;
    for (int b = b0; b < b1; b++) {
        s += (double)g_psum[b * DIM_H + c];
        q += (double)g_psq [b * DIM_H + c];
    }
    sh_s[part][c] = s; sh_q[part][c] = q;
    __syncthreads();
    if (part == 0) {
        s = sh_s[0][c] + sh_s[1][c] + sh_s[2][c] + sh_s[3][c];
        q = sh_q[0][c] + sh_q[1][c] + sh_q[2][c] + sh_q[3][c];
        // GEMM1 omits bias b1: it shifts the mean by exactly b1 and cancels in BN.
        double mean = s / (double)N_NODES;
        double var  = q / (double)N_NODES - mean * mean;
        float sc = gamma[c] * (float)rsqrt(var + (double)BN_EPS);
        g_scale[c] = sc;
        g_shift[c] = beta[c] - (float)mean * sc;
    }
}

// ---------------- BN + ReLU in place on h1 (RNA-rounded output) --------------
__global__ void bn_relu_kernel() {
    int i = blockIdx.x * blockDim.x + threadIdx.x;
    const int n4 = N_NODES * DIM_H / 4;
    if (i >= n4) return;
    float4 v = reinterpret_cast<float4*>(g_h1)[i];
    int c = (i * 4) & (DIM_H - 1);
    v.x = __uint_as_float(rna_tf32(fmaxf(fmaf(v.x, g_scale[c + 0], g_shift[c + 0]), 0.f)));
    v.y = __uint_as_float(rna_tf32(fmaxf(fmaf(v.y, g_scale[c + 1], g_shift[c + 1]), 0.f)));
    v.z = __uint_as_float(rna_tf32(fmaxf(fmaf(v.z, g_scale[c + 2], g_shift[c + 2]), 0.f)));
    v.w = __uint_as_float(rna_tf32(fmaxf(fmaf(v.w, g_scale[c + 3], g_shift[c + 3]), 0.f)));
    reinterpret_cast<float4*>(g_h1)[i] = v;
}

// ---------------- launch ----------------
extern "C" void kernel_launch(void* const* d_in, const int* in_sizes, int n_in,
                              void* d_out, int out_size) {
    const float* x     = (const float*)d_in[0];
    const void*  ei    = d_in[1];
    const float* W1    = (const float*)d_in[2];
    const float* gamma = (const float*)d_in[4];
    const float* beta  = (const float*)d_in[5];
    const float* W2    = (const float*)d_in[6];
    const float* b2    = (const float*)d_in[7];
    const float* Wlin  = (const float*)d_in[8];
    const float* blin  = (const float*)d_in[9];
    float* out = (float*)d_out;

    float *h0, *h1, *h2, *Bt1, *Bt2, *Bt3;
    cudaGetSymbolAddress((void**)&h0, g_h0);
    cudaGetSymbolAddress((void**)&h1, g_h1);
    cudaGetSymbolAddress((void**)&h2, g_h2);
    cudaGetSymbolAddress((void**)&Bt1, g_Bt1);
    cudaGetSymbolAddress((void**)&Bt2, g_Bt2);
    cudaGetSymbolAddress((void**)&Bt3, g_Bt3);

    constexpr int SMEM_N128 = 2 * (128 * 128 + 128 * 128);  // 65536
    constexpr int SMEM_N64  = 2 * (128 * 128 + 64 * 128);   // 49152
    cudaFuncSetAttribute(mma_gemm_big<false, false, true>,
                         cudaFuncAttributeMaxDynamicSharedMemorySize, SMEM_N128);
    cudaFuncSetAttribute(mma_gemm_big<true, true, false>,
                         cudaFuncAttributeMaxDynamicSharedMemorySize, SMEM_N128);
    cudaFuncSetAttribute(mma_gemm_kernel<64, 4, 2, true, false>,
                         cudaFuncAttributeMaxDynamicSharedMemorySize, SMEM_N64);

    // 1) prep: dtype detect + transposes (tf32 RNA-rounded)
    prep_kernel<<<425, 256>>>((const int*)ei, W1, W2, Wlin);

    // 2) h0 = x ; h0[dst] += x[src]
    copy_x_kernel<<<(N_NODES * F_IN / 4 + 255) / 256, 256>>>((const float4*)x);
    scatter_kernel<<<(N_EDGES * 32 + 255) / 256, 256>>>(x, ei);

    // 3) h1 = h0 @ W1  (+ fused per-CTA BN stats; b1 cancels through BN)
    mma_gemm_big<false, false, true><<<dim3(GRID_M, 2), 128, SMEM_N128>>>(
        h0, Bt1, nullptr, h1, M_PAD, F_IN, DIM_H);

    // 4) reduce partials -> scale/shift ; BN+ReLU in place (tf32-rounded)
    finalize_psum_kernel<<<1, 1024>>>(gamma, beta);
    bn_relu_kernel<<<(N_NODES * DIM_H / 4 + 255) / 256, 256>>>();

    // 5) h2 = relu(h1bn @ W2 + b2)   — big-tile 64x64 warp GEMM
    mma_gemm_big<true, true, false><<<dim3(GRID_M, 2), 128, SMEM_N128>>>(
        h1, Bt2, b2, h2, M_PAD, DIM_H, DIM_H);

    // 6) out = h2 @ Wlin + blin
    mma_gemm_kernel<64, 4, 2, true, false><<<dim3(GRID_M, 1), 256, SMEM_N64>>>(
        h2, Bt3, blin, out, N_NODES, DIM_H, N_CLASSES);
}

// round 13
// speedup vs baseline: 1.5731x; 1.5731x over previous
#include <cuda_runtime.h>
#include <cstdint>

#define N_NODES 50000
#define M_PAD   50048          // 391 * 128
#define N_EDGES 600000
#define F_IN 128
#define DIM_H 256
#define N_CLASSES 40
#define BN_EPS 1e-5f

// ---------------- scratch (static __device__, no allocation) ----------------
__device__ float  g_h0[(size_t)M_PAD * F_IN];     // x + agg   (padding rows stay 0)
__device__ float  g_h1[(size_t)M_PAD * DIM_H];    // GEMM1 out (raw, pre-BN)
__device__ float  g_h2[(size_t)M_PAD * DIM_H];    // GEMM2 out
__device__ float  g_Bt1[DIM_H * F_IN];            // W1^T  [256][128]  (tf32-rounded)
__device__ float  g_Bt2[DIM_H * DIM_H];           // W2^T  [256][256]
__device__ float  g_Bt3[N_CLASSES * DIM_H];       // Wlin^T [40][256]
__device__ double g_sum[DIM_H];
__device__ double g_sumsq[DIM_H];
__device__ float  g_scale[DIM_H];
__device__ float  g_shift[DIM_H];
__device__ int    g_is64;

// ---------------- PTX helpers (all sm_80-compatible, no arch-'a' features) ----
__device__ __forceinline__ uint32_t smem_u32(const void* p) {
    uint32_t a;
    asm("{ .reg .u64 t; cvta.to.shared.u64 t, %1; cvt.u32.u64 %0, t; }" : "=r"(a) : "l"(p));
    return a;
}
__device__ __forceinline__ void cp_async16(uint32_t dst, const void* src) {
    asm volatile("cp.async.cg.shared.global [%0], [%1], 16;" :: "r"(dst), "l"(src));
}
__device__ __forceinline__ void cp_commit() {
    asm volatile("cp.async.commit_group;" ::: "memory");
}
template<int N>
__device__ __forceinline__ void cp_wait() {
    asm volatile("cp.async.wait_group %0;" :: "n"(N) : "memory");
}
__device__ __forceinline__ void ldsm_x4(uint32_t& r0, uint32_t& r1, uint32_t& r2, uint32_t& r3,
                                        uint32_t addr) {
    asm volatile("ldmatrix.sync.aligned.m8n8.x4.shared.b16 {%0,%1,%2,%3}, [%4];"
                 : "=r"(r0), "=r"(r1), "=r"(r2), "=r"(r3) : "r"(addr));
}
__device__ __forceinline__ void mma_tf32(float* c, const uint32_t* a, const uint32_t* b) {
    asm volatile("mma.sync.aligned.m16n8k8.row.col.f32.tf32.tf32.f32 "
                 "{%0,%1,%2,%3}, {%4,%5,%6,%7}, {%8,%9}, {%0,%1,%2,%3};"
                 : "+f"(c[0]), "+f"(c[1]), "+f"(c[2]), "+f"(c[3])
                 : "r"(a[0]), "r"(a[1]), "r"(a[2]), "r"(a[3]), "r"(b[0]), "r"(b[1]));
}
__device__ __forceinline__ uint32_t rna_tf32(float f) {
    uint32_t r;
    asm("cvt.rna.tf32.f32 %0, %1;" : "=r"(r) : "f"(f));
    return r;
}

// ---------------- prep: dtype detect + zero stats + weight transposes --------
__global__ void prep_kernel(const int* __restrict__ ei,
                            const float* __restrict__ W1,
                            const float* __restrict__ W2,
                            const float* __restrict__ Wlin) {
    int tid = threadIdx.x;
    if (blockIdx.x == 0) {
        g_sum[tid] = 0.0; g_sumsq[tid] = 0.0;
        __shared__ int nz;
        if (tid == 0) nz = 0;
        __syncthreads();
        if (ei[2 * tid + 1] != 0) atomicOr(&nz, 1);
        __syncthreads();
        if (tid == 0) g_is64 = (nz == 0) ? 1 : 0;
    }
    int g = blockIdx.x * blockDim.x + tid;
    int stride = gridDim.x * blockDim.x;
    uint32_t* B1 = reinterpret_cast<uint32_t*>(g_Bt1);
    uint32_t* B2 = reinterpret_cast<uint32_t*>(g_Bt2);
    uint32_t* B3 = reinterpret_cast<uint32_t*>(g_Bt3);
    for (int i = g; i < F_IN * DIM_H; i += stride) {
        int k = i / DIM_H, n = i - k * DIM_H;
        B1[n * F_IN + k] = rna_tf32(W1[i]);
    }
    for (int i = g; i < DIM_H * DIM_H; i += stride) {
        int k = i / DIM_H, n = i - k * DIM_H;
        B2[n * DIM_H + k] = rna_tf32(W2[i]);
    }
    for (int i = g; i < DIM_H * N_CLASSES; i += stride) {
        int k = i / N_CLASSES, n = i - k * N_CLASSES;
        B3[n * DIM_H + k] = rna_tf32(Wlin[i]);
    }
}

// ---------------- h0 = x ----------------
__global__ void copy_x_kernel(const float4* __restrict__ x4) {
    int i = blockIdx.x * blockDim.x + threadIdx.x;
    const int n = N_NODES * F_IN / 4;
    if (i < n) reinterpret_cast<float4*>(g_h0)[i] = x4[i];
}

// ---------------- scatter: h0[dst] += x[src], warp per edge ----------------
__global__ void scatter_kernel(const float* __restrict__ x, const void* __restrict__ eiv) {
    int gid = blockIdx.x * blockDim.x + threadIdx.x;
    int e = gid >> 5;
    if (e >= N_EDGES) return;
    int lane = gid & 31;
    long long s, d;
    if (g_is64) {
        const long long* ei = (const long long*)eiv;
        s = ei[e]; d = ei[N_EDGES + e];
    } else {
        const int* ei = (const int*)eiv;
        s = ei[e]; d = ei[N_EDGES + e];
    }
    float4 v = reinterpret_cast<const float4*>(x + s * F_IN)[lane];
    float* p = g_h0 + d * F_IN + lane * 4;
    asm volatile("red.global.add.v4.f32 [%0], {%1, %2, %3, %4};"
                 :: "l"(p), "f"(v.x), "f"(v.y), "f"(v.z), "f"(v.w) : "memory");
}

// ---------------- tf32 mma.sync GEMM (R8 proven): 256 thr, warp tile 64x32 ---
// Used for the ragged-N GEMM3 only.
template<int BN, int WARPS_M, int WARPS_N, bool HAS_BIAS, bool RELU>
__global__ void __launch_bounds__(256, 2) mma_gemm_kernel(
    const float* __restrict__ A, const float* __restrict__ Bt,
    const float* __restrict__ bias, float* __restrict__ C,
    int M, int K, int Nreal)
{
    constexpr int KC = 32;                 // floats per K chunk (= 128B row)
    constexpr int WTM = 128 / WARPS_M;
    constexpr int WTN = BN / WARPS_N;
    constexpr int RM = WTM / 16;
    constexpr int RN = WTN / 8;
    constexpr int A_BYTES = 128 * 128;
    constexpr int B_BYTES = BN * 128;
    constexpr int BUF = A_BYTES + B_BYTES;
    extern __shared__ __align__(128) char smem[];
    const uint32_t sbase = smem_u32(smem);

    const int tid = threadIdx.x, wid = tid >> 5, lane = tid & 31;
    const int wm = wid % WARPS_M, wn = wid / WARPS_M;
    const int m0 = blockIdx.x * 128;
    const int n0cta = blockIdx.y * BN;
    const int nb_valid = Nreal - n0cta;    // B rows present in this CTA's n-slice
    const int nchunks = K / KC;

    // zero B buffers only when the n-slice is ragged (GEMM3)
    if (nb_valid < BN) {
        for (int i = tid; i < 2 * B_BYTES / 16; i += 256) {
            int b = i / (B_BYTES / 16), j = i % (B_BYTES / 16);
            *reinterpret_cast<float4*>(smem + b * BUF + A_BYTES + j * 16) =
                make_float4(0.f, 0.f, 0.f, 0.f);
        }
    }
    __syncthreads();

    auto load_chunk = [&](int c) {
        const uint32_t abuf = sbase + (c & 1) * BUF;
        const uint32_t bbuf = abuf + A_BYTES;
        const float* Ab = A + (size_t)m0 * K + c * KC;
        #pragma unroll
        for (int i = 0; i < 4; i++) {
            int f = tid + i * 256;         // 0..1023
            int row = f >> 3, kc = f & 7;
            cp_async16(abuf + row * 128 + ((kc ^ (row & 7)) << 4),
                       Ab + (size_t)row * K + kc * 4);
        }
        const float* Bb = Bt + (size_t)n0cta * K + c * KC;
        #pragma unroll
        for (int i = 0; i < BN * 8 / 256; i++) {
            int f = tid + i * 256;
            int row = f >> 3, kc = f & 7;
            if (row < nb_valid)
                cp_async16(bbuf + row * 128 + ((kc ^ (row & 7)) << 4),
                           Bb + (size_t)row * K + kc * 4);
        }
        cp_commit();
    };

    load_chunk(0);
    load_chunk(1);

    float acc[RM][RN][4] = {};

    for (int c = 0; c < nchunks; c++) {
        if (c + 1 < nchunks) cp_wait<1>(); else cp_wait<0>();
        __syncthreads();

        const uint32_t abuf = sbase + (c & 1) * BUF;
        const uint32_t bbuf = abuf + A_BYTES;
        #pragma unroll
        for (int ks = 0; ks < 4; ks++) {
            uint32_t af[RM][4], bf[RN][2];
            #pragma unroll
            for (int mt = 0; mt < RM; mt++) {
                int row = wm * WTM + mt * 16 + (lane & 15);
                int kc = ks * 2 + (lane >> 4);
                ldsm_x4(af[mt][0], af[mt][1], af[mt][2], af[mt][3],
                        abuf + row * 128 + ((kc ^ (row & 7)) << 4));
            }
            #pragma unroll
            for (int nt = 0; nt < RN; nt += 2) {
                int row = wn * WTN + nt * 8 + ((lane >> 4) & 1) * 8 + (lane & 7);
                int kc = ks * 2 + ((lane >> 3) & 1);
                ldsm_x4(bf[nt][0], bf[nt][1], bf[nt + 1][0], bf[nt + 1][1],
                        bbuf + row * 128 + ((kc ^ (row & 7)) << 4));
            }
            #pragma unroll
            for (int mt = 0; mt < RM; mt++)
                #pragma unroll
                for (int nt = 0; nt < RN; nt++)
                    mma_tf32(acc[mt][nt], af[mt], bf[nt]);
        }
        __syncthreads();
        if (c + 2 < nchunks) load_chunk(c + 2);
    }

    // epilogue
    #pragma unroll
    for (int mt = 0; mt < RM; mt++) {
        int r0 = m0 + wm * WTM + mt * 16 + (lane >> 2);
        #pragma unroll
        for (int nt = 0; nt < RN; nt++) {
            int n = n0cta + wn * WTN + nt * 8 + (lane & 3) * 2;
            if (n >= Nreal) continue;      // Nreal even -> pair fully valid
            float2 v0 = make_float2(acc[mt][nt][0], acc[mt][nt][1]);
            float2 v1 = make_float2(acc[mt][nt][2], acc[mt][nt][3]);
            if (HAS_BIAS) {
                float2 bb = *reinterpret_cast<const float2*>(bias + n);
                v0.x += bb.x; v0.y += bb.y; v1.x += bb.x; v1.y += bb.y;
            }
            if (RELU) {
                v0.x = fmaxf(v0.x, 0.f); v0.y = fmaxf(v0.y, 0.f);
                v1.x = fmaxf(v1.x, 0.f); v1.y = fmaxf(v1.y, 0.f);
            }
            if (r0 < M)
                *reinterpret_cast<float2*>(C + (size_t)r0 * Nreal + n) = v0;
            if (r0 + 8 < M)
                *reinterpret_cast<float2*>(C + (size_t)(r0 + 8) * Nreal + n) = v1;
        }
    }
}

// ---------------- big-tile tf32 GEMM (GEMM1 + GEMM2): 128 thr, 64x64/warp ----
// CTA 128x128, 2x2 warps, RM=4, RN=8. Requires Nreal % 128 == 0.
// PRE_BN (GEMM2): A fragments -> rna(relu(a * g_scale[k] + g_shift[k])).
// Fragment k-map (m16n8k8): regs {0,1} -> k1, regs {2,3} -> k1+4,
// k1 = c*KC + ks*8 + (lane & 3)   (validated in R5 at rel_err 4.9e-4).
template<bool HAS_BIAS, bool RELU, bool PRE_BN>
__global__ void __launch_bounds__(128, 2) mma_gemm_big(
    const float* __restrict__ A, const float* __restrict__ Bt,
    const float* __restrict__ bias, float* __restrict__ C,
    int M, int K, int Nreal)
{
    constexpr int KC = 32;
    constexpr int BN = 128;
    constexpr int RM = 4, RN = 8;          // 64x64 per warp
    constexpr int A_BYTES = 128 * 128;
    constexpr int B_BYTES = BN * 128;
    constexpr int BUF = A_BYTES + B_BYTES;
    extern __shared__ __align__(128) char smem[];
    const uint32_t sbase = smem_u32(smem);

    const int tid = threadIdx.x, wid = tid >> 5, lane = tid & 31;
    const int wm = wid & 1, wn = wid >> 1; // 2x2 warp grid
    const int m0 = blockIdx.x * 128;
    const int n0cta = blockIdx.y * BN;
    const int nchunks = K / KC;

    auto load_chunk = [&](int c) {
        const uint32_t abuf = sbase + (c & 1) * BUF;
        const uint32_t bbuf = abuf + A_BYTES;
        const float* Ab = A + (size_t)m0 * K + c * KC;
        #pragma unroll
        for (int i = 0; i < 8; i++) {
            int f = tid + i * 128;         // 0..1023
            int row = f >> 3, kc = f & 7;
            cp_async16(abuf + row * 128 + ((kc ^ (row & 7)) << 4),
                       Ab + (size_t)row * K + kc * 4);
        }
        const float* Bb = Bt + (size_t)n0cta * K + c * KC;
        #pragma unroll
        for (int i = 0; i < 8; i++) {
            int f = tid + i * 128;
            int row = f >> 3, kc = f & 7;
            cp_async16(bbuf + row * 128 + ((kc ^ (row & 7)) << 4),
                       Bb + (size_t)row * K + kc * 4);
        }
        cp_commit();
    };

    load_chunk(0);
    load_chunk(1);

    float acc[RM][RN][4] = {};

    for (int c = 0; c < nchunks; c++) {
        if (c + 1 < nchunks) cp_wait<1>(); else cp_wait<0>();
        __syncthreads();

        const uint32_t abuf = sbase + (c & 1) * BUF;
        const uint32_t bbuf = abuf + A_BYTES;
        #pragma unroll
        for (int ks = 0; ks < 4; ks++) {
            uint32_t af[RM][4], bf[RN][2];
            #pragma unroll
            for (int mt = 0; mt < RM; mt++) {
                int row = wm * 64 + mt * 16 + (lane & 15);
                int kc = ks * 2 + (lane >> 4);
                ldsm_x4(af[mt][0], af[mt][1], af[mt][2], af[mt][3],
                        abuf + row * 128 + ((kc ^ (row & 7)) << 4));
            }
            if constexpr (PRE_BN) {
                int k1 = c * KC + ks * 8 + (lane & 3);
                float s1 = __ldg(&g_scale[k1]),     t1 = __ldg(&g_shift[k1]);
                float s2 = __ldg(&g_scale[k1 + 4]), t2 = __ldg(&g_shift[k1 + 4]);
                #pragma unroll
                for (int mt = 0; mt < RM; mt++) {
                    af[mt][0] = rna_tf32(fmaxf(fmaf(__uint_as_float(af[mt][0]), s1, t1), 0.f));
                    af[mt][1] = rna_tf32(fmaxf(fmaf(__uint_as_float(af[mt][1]), s1, t1), 0.f));
                    af[mt][2] = rna_tf32(fmaxf(fmaf(__uint_as_float(af[mt][2]), s2, t2), 0.f));
                    af[mt][3] = rna_tf32(fmaxf(fmaf(__uint_as_float(af[mt][3]), s2, t2), 0.f));
                }
            }
            #pragma unroll
            for (int nt = 0; nt < RN; nt += 2) {
                int row = wn * 64 + nt * 8 + ((lane >> 4) & 1) * 8 + (lane & 7);
                int kc = ks * 2 + ((lane >> 3) & 1);
                ldsm_x4(bf[nt][0], bf[nt][1], bf[nt + 1][0], bf[nt + 1][1],
                        bbuf + row * 128 + ((kc ^ (row & 7)) << 4));
            }
            #pragma unroll
            for (int mt = 0; mt < RM; mt++)
                #pragma unroll
                for (int nt = 0; nt < RN; nt++)
                    mma_tf32(acc[mt][nt], af[mt], bf[nt]);
        }
        __syncthreads();
        if (c + 2 < nchunks) load_chunk(c + 2);
    }

    // epilogue
    #pragma unroll
    for (int mt = 0; mt < RM; mt++) {
        int r0 = m0 + wm * 64 + mt * 16 + (lane >> 2);
        #pragma unroll
        for (int nt = 0; nt < RN; nt++) {
            int n = n0cta + wn * 64 + nt * 8 + (lane & 3) * 2;
            float2 v0 = make_float2(acc[mt][nt][0], acc[mt][nt][1]);
            float2 v1 = make_float2(acc[mt][nt][2], acc[mt][nt][3]);
            if (HAS_BIAS) {
                float2 bb = *reinterpret_cast<const float2*>(bias + n);
                v0.x += bb.x; v0.y += bb.y; v1.x += bb.x; v1.y += bb.y;
            }
            if (RELU) {
                v0.x = fmaxf(v0.x, 0.f); v0.y = fmaxf(v0.y, 0.f);
                v1.x = fmaxf(v1.x, 0.f); v1.y = fmaxf(v1.y, 0.f);
            }
            if (r0 < M)
                *reinterpret_cast<float2*>(C + (size_t)r0 * Nreal + n) = v0;
            if (r0 + 8 < M)
                *reinterpret_cast<float2*>(C + (size_t)(r0 + 8) * Nreal + n) = v1;
        }
    }
}

// ---------------- BN stats (reads raw h1) ----------------
__global__ void stats_kernel(const float* __restrict__ h1) {
    int c = threadIdx.x;              // 256 = DIM_H
    int r0 = blockIdx.x * 256;
    int r1 = min(r0 + 256, N_NODES);
    float s = 0.f, ss = 0.f;
    for (int r = r0; r < r1; r++) {
        float v = h1[(size_t)r * DIM_H + c];
        s += v; ss += v * v;
    }
    atomicAdd(&g_sum[c], (double)s);
    atomicAdd(&g_sumsq[c], (double)ss);
}

__global__ void finalize_stats_kernel(const float* __restrict__ gamma,
                                      const float* __restrict__ beta) {
    int c = threadIdx.x;              // 256
    // GEMM1 omits bias b1: it shifts the mean by exactly b1 and cancels in BN.
    double mean = g_sum[c] / (double)N_NODES;
    double var  = g_sumsq[c] / (double)N_NODES - mean * mean;
    float sc = gamma[c] * (float)rsqrt(var + (double)BN_EPS);
    g_scale[c] = sc;
    g_shift[c] = beta[c] - (float)mean * sc;
}

// ---------------- launch ----------------
extern "C" void kernel_launch(void* const* d_in, const int* in_sizes, int n_in,
                              void* d_out, int out_size) {
    const float* x     = (const float*)d_in[0];
    const void*  ei    = d_in[1];
    const float* W1    = (const float*)d_in[2];
    const float* gamma = (const float*)d_in[4];
    const float* beta  = (const float*)d_in[5];
    const float* W2    = (const float*)d_in[6];
    const float* b2    = (const float*)d_in[7];
    const float* Wlin  = (const float*)d_in[8];
    const float* blin  = (const float*)d_in[9];
    float* out = (float*)d_out;

    float *h0, *h1, *h2, *Bt1, *Bt2, *Bt3;
    cudaGetSymbolAddress((void**)&h0, g_h0);
    cudaGetSymbolAddress((void**)&h1, g_h1);
    cudaGetSymbolAddress((void**)&h2, g_h2);
    cudaGetSymbolAddress((void**)&Bt1, g_Bt1);
    cudaGetSymbolAddress((void**)&Bt2, g_Bt2);
    cudaGetSymbolAddress((void**)&Bt3, g_Bt3);

    constexpr int SMEM_N128 = 2 * (128 * 128 + 128 * 128);  // 65536
    constexpr int SMEM_N64  = 2 * (128 * 128 + 64 * 128);   // 49152
    cudaFuncSetAttribute(mma_gemm_big<false, false, false>,
                         cudaFuncAttributeMaxDynamicSharedMemorySize, SMEM_N128);
    cudaFuncSetAttribute(mma_gemm_big<true, true, true>,
                         cudaFuncAttributeMaxDynamicSharedMemorySize, SMEM_N128);
    cudaFuncSetAttribute(mma_gemm_kernel<64, 4, 2, true, false>,
                         cudaFuncAttributeMaxDynamicSharedMemorySize, SMEM_N64);

    // 1) prep: dtype detect + zero stats + transposes (tf32 RNA-rounded)
    prep_kernel<<<425, 256>>>((const int*)ei, W1, W2, Wlin);

    // 2) h0 = x ; h0[dst] += x[src]
    copy_x_kernel<<<(N_NODES * F_IN / 4 + 255) / 256, 256>>>((const float4*)x);
    scatter_kernel<<<(N_EDGES * 32 + 255) / 256, 256>>>(x, ei);

    const int GRID_M = M_PAD / 128;   // 391

    // 3) h1 = h0 @ W1   (b1 cancels through BN) — big-tile 64x64 warp GEMM
    mma_gemm_big<false, false, false><<<dim3(GRID_M, 2), 128, SMEM_N128>>>(
        h0, Bt1, nullptr, h1, M_PAD, F_IN, DIM_H);

    // 4) BN stats -> scale/shift (no separate bn_relu pass)
    stats_kernel<<<(N_NODES + 255) / 256, 256>>>(h1);
    finalize_stats_kernel<<<1, DIM_H>>>(gamma, beta);

    // 5) h2 = relu( BN(h1) @ W2 + b2 )   — BN+ReLU fused on A fragments
    mma_gemm_big<true, true, true><<<dim3(GRID_M, 2), 128, SMEM_N128>>>(
        h1, Bt2, b2, h2, M_PAD, DIM_H, DIM_H);

    // 6) out = h2 @ Wlin + blin
    mma_gemm_kernel<64, 4, 2, true, false><<<dim3(GRID_M, 1), 256, SMEM_N64>>>(
        h2, Bt3, blin, out, N_NODES, DIM_H, N_CLASSES);
}